// round 2
// baseline (speedup 1.0000x reference)
#include <cuda_runtime.h>
#include <math.h>

// Elman RNN, fp32. B=128, S=1024, I=256, H=512, O=256, N_TARGETS=1.
// Phase A: P[t][j][b] = sum_i x[b,t,i]*W_i2h[j,i] + b_i2h[j]   (parallel GEMM)
// Phase B: persistent kernel, 1024 sequential steps:
//          h[b][j] = tanh(P[t][j][b] + sum_k h_prev[b][k]*W_i2h[j][I+k])
// Phase C: output = h_T @ W_h2o^T + b_h2o ; also emit hidden = h_T.

namespace {
constexpr int S = 1024, B = 128, I = 256, H = 512, O = 256;
constexpr int G = 128;    // persistent grid (<= 148 SMs, all co-resident)
constexpr int KT = 16;    // k chunks
constexpr int KC = 32;    // chunk size (KT*KC = H)
constexpr int JC = 128;   // j tile
}

__device__ float g_P[(size_t)S * H * B];      // [t][j][b] pre-activations (256 MB)
__device__ float g_Ht[H * B];                 // transposed hidden state [k][b]
__device__ float g_Part[(size_t)KT * H * B];  // k-split partials [kk][j][b] (4 MB)
__device__ unsigned g_arrive;                 // grid barrier counter (monotonic)

__device__ __forceinline__ void grid_barrier(unsigned target) {
    __syncthreads();
    if (threadIdx.x == 0) {
        __threadfence();
        atomicAdd(&g_arrive, 1u);
        unsigned v;
        do {
            asm volatile("ld.acquire.gpu.u32 %0, [%1];"
                         : "=r"(v) : "l"(&g_arrive) : "memory");
        } while (v < target);
    }
    __syncthreads();
}

// ---------------- Phase A: pre-activation GEMM ----------------
// grid (S, H/128), 256 threads. CTA computes 128 j x 128 b for one t, K=I=256.
__global__ void __launch_bounds__(256) phaseA_kernel(
    const float* __restrict__ seq, const float* __restrict__ Wi2h,
    const float* __restrict__ bi2h) {
    const int t = blockIdx.x;
    const int j0 = blockIdx.y * 128;
    const int tid = threadIdx.x;
    const int tx = tid & 15;   // 8 b per thread
    const int ty = tid >> 4;   // 8 j per thread
    __shared__ float sh_a[128 * 16];  // [j][k]
    __shared__ float sh_b[16 * 128];  // [k][b]
    float acc[8][8];
#pragma unroll
    for (int r = 0; r < 8; r++)
#pragma unroll
        for (int c = 0; c < 8; c++) acc[r][c] = 0.f;

    for (int k0 = 0; k0 < I; k0 += 16) {
        __syncthreads();
#pragma unroll
        for (int q = 0; q < 2; q++) {
            int idx = tid + q * 256;  // 0..511
            int j = idx >> 2, kq = idx & 3;
            float4 v = *(const float4*)(Wi2h + (size_t)(j0 + j) * (I + H) + k0 + kq * 4);
            *(float4*)(sh_a + j * 16 + kq * 4) = v;
        }
#pragma unroll
        for (int q = 0; q < 2; q++) {
            int idx = tid + q * 256;
            int b = idx >> 2, kq = idx & 3;
            float4 v = *(const float4*)(seq + (size_t)b * (S * I) + (size_t)t * I + k0 + kq * 4);
            sh_b[(kq * 4 + 0) * 128 + b] = v.x;
            sh_b[(kq * 4 + 1) * 128 + b] = v.y;
            sh_b[(kq * 4 + 2) * 128 + b] = v.z;
            sh_b[(kq * 4 + 3) * 128 + b] = v.w;
        }
        __syncthreads();
#pragma unroll
        for (int k = 0; k < 16; k++) {
            float av[8];
#pragma unroll
            for (int r = 0; r < 8; r++) av[r] = sh_a[(ty * 8 + r) * 16 + k];
            float4 bv0 = *(const float4*)(sh_b + k * 128 + tx * 8);
            float4 bv1 = *(const float4*)(sh_b + k * 128 + tx * 8 + 4);
            float bv[8] = {bv0.x, bv0.y, bv0.z, bv0.w, bv1.x, bv1.y, bv1.z, bv1.w};
#pragma unroll
            for (int r = 0; r < 8; r++)
#pragma unroll
                for (int c = 0; c < 8; c++) acc[r][c] = fmaf(av[r], bv[c], acc[r][c]);
        }
    }
#pragma unroll
    for (int r = 0; r < 8; r++) {
        int j = j0 + ty * 8 + r;
        float bj = bi2h[j];
        float* op = g_P + (size_t)t * (H * B) + (size_t)j * B + tx * 8;
        float4 v0 = {acc[r][0] + bj, acc[r][1] + bj, acc[r][2] + bj, acc[r][3] + bj};
        float4 v1 = {acc[r][4] + bj, acc[r][5] + bj, acc[r][6] + bj, acc[r][7] + bj};
        *(float4*)op = v0;
        *(float4*)(op + 4) = v1;
    }
}

// ---------------- Phase B: persistent recurrence ----------------
// 128 CTAs = 2 batch-halves x 4 j-tiles(128) x 16 k-chunks(32).
// Per step: stage1 partial GEMM -> barrier -> stage2 reduce+tanh -> barrier.
__global__ void __launch_bounds__(256) phaseB_kernel(const float* __restrict__ Wi2h) {
    const int cta = blockIdx.x;
    const int kk = cta & 15;
    const int jj = (cta >> 4) & 3;
    const int bb = cta >> 6;
    const int k0 = kk * KC;
    const int j0 = jj * JC;
    const int b0 = bb * 64;
    const int tid = threadIdx.x;
    const int tx = tid & 15;  // 4 b per thread
    const int ty = tid >> 4;  // 8 j per thread
    __shared__ float sh_w[KC * JC];  // [k][j] 16KB, persistent across steps
    __shared__ float sh_h[KC * 64];  // [k][b] 8KB, restaged each step

    // Load Wh tile once: Wh[k][j] = Wi2h[(j0+j)*(I+H) + I + k0 + k]
#pragma unroll
    for (int q = 0; q < 4; q++) {
        int idx = tid + q * 256;  // 0..1023
        int j = idx >> 3, kq = idx & 7;
        float4 v = *(const float4*)(Wi2h + (size_t)(j0 + j) * (I + H) + I + k0 + kq * 4);
        sh_w[(kq * 4 + 0) * JC + j] = v.x;
        sh_w[(kq * 4 + 1) * JC + j] = v.y;
        sh_w[(kq * 4 + 2) * JC + j] = v.z;
        sh_w[(kq * 4 + 3) * JC + j] = v.w;
    }

    unsigned bar = 0;
    for (int t = 0; t < S; t++) {
        // stage 1: stage h chunk [k0..k0+32) x [b0..b0+64) into smem
#pragma unroll
        for (int q = 0; q < 2; q++) {
            int idx = tid + q * 256;  // 0..511
            int k = idx >> 4, bq = idx & 15;
            *(float4*)(sh_h + k * 64 + bq * 4) =
                *(const float4*)(g_Ht + (k0 + k) * B + b0 + bq * 4);
        }
        __syncthreads();
        float acc[4][8];
#pragma unroll
        for (int r = 0; r < 4; r++)
#pragma unroll
            for (int c = 0; c < 8; c++) acc[r][c] = 0.f;
#pragma unroll 8
        for (int k = 0; k < KC; k++) {
            float4 hv = *(const float4*)(sh_h + k * 64 + tx * 4);
            float4 wv0 = *(const float4*)(sh_w + k * JC + ty * 8);
            float4 wv1 = *(const float4*)(sh_w + k * JC + ty * 8 + 4);
            float hvv[4] = {hv.x, hv.y, hv.z, hv.w};
            float wvv[8] = {wv0.x, wv0.y, wv0.z, wv0.w, wv1.x, wv1.y, wv1.z, wv1.w};
#pragma unroll
            for (int r = 0; r < 4; r++)
#pragma unroll
                for (int c = 0; c < 8; c++) acc[r][c] = fmaf(hvv[r], wvv[c], acc[r][c]);
        }
        {
            float* pp = g_Part + (size_t)kk * (H * B) + (size_t)(j0 + ty * 8) * B + b0 + tx * 4;
#pragma unroll
            for (int c = 0; c < 8; c++) {
                float4 v = {acc[0][c], acc[1][c], acc[2][c], acc[3][c]};
                *(float4*)(pp + c * B) = v;
            }
        }
        grid_barrier(++bar * G);

        // stage 2: reduce KT partials + pre-activation, tanh, write new Ht
        {
            int o = cta * 512 + tid;
            const float* pP = g_P + (size_t)t * (H * B);
            float a0 = pP[o];
            float a1 = pP[o + 256];
#pragma unroll
            for (int q = 0; q < KT; q++) {
                a0 += g_Part[(size_t)q * (H * B) + o];
                a1 += g_Part[(size_t)q * (H * B) + o + 256];
            }
            g_Ht[o] = tanhf(a0);
            g_Ht[o + 256] = tanhf(a1);
        }
        grid_barrier(++bar * G);
    }
}

// ---------------- Phase C: output projection + hidden emit ----------------
__global__ void __launch_bounds__(256) phaseC_kernel(
    const float* __restrict__ Wh2o, const float* __restrict__ bh2o,
    float* __restrict__ out, int out_size) {
    int idx = blockIdx.x * 256 + threadIdx.x;  // 0..32767
    int b = idx >> 8, o = idx & 255;
    float acc = bh2o[o];
    const float4* wrow = (const float4*)(Wh2o + (size_t)o * H);
#pragma unroll 4
    for (int k4 = 0; k4 < H / 4; k4++) {
        float4 w = wrow[k4];
        int kb = k4 * 4;
        acc = fmaf(g_Ht[(kb + 0) * B + b], w.x, acc);
        acc = fmaf(g_Ht[(kb + 1) * B + b], w.y, acc);
        acc = fmaf(g_Ht[(kb + 2) * B + b], w.z, acc);
        acc = fmaf(g_Ht[(kb + 3) * B + b], w.w, acc);
    }
    if (idx < out_size) out[idx] = acc;  // output (B,1,O) flattened: idx = b*256+o
    // hidden (B,H) appended after the output, if the harness expects it
    if (out_size >= B * O + B * H) {
#pragma unroll
        for (int q = 0; q < 2; q++) {
            int e = idx + q * (B * O);  // 0..65535
            int hb = e >> 9, hk = e & 511;
            out[B * O + e] = g_Ht[hk * B + hb];
        }
    }
}

extern "C" void kernel_launch(void* const* d_in, const int* in_sizes, int n_in,
                              void* d_out, int out_size) {
    const float* seq  = (const float*)d_in[0];
    const float* Wi2h = (const float*)d_in[1];
    const float* bi2h = (const float*)d_in[2];
    const float* Wh2o = (const float*)d_in[3];
    const float* bh2o = (const float*)d_in[4];
    float* out = (float*)d_out;

    void* pArr = nullptr;
    cudaGetSymbolAddress(&pArr, g_arrive);
    cudaMemsetAsync(pArr, 0, sizeof(unsigned), 0);
    void* pHt = nullptr;
    cudaGetSymbolAddress(&pHt, g_Ht);
    cudaMemsetAsync(pHt, 0, (size_t)H * B * sizeof(float), 0);

    phaseA_kernel<<<dim3(S, H / 128), 256>>>(seq, Wi2h, bi2h);
    phaseB_kernel<<<G, 256>>>(Wi2h);
    phaseC_kernel<<<(B * O) / 256, 256>>>(Wh2o, bh2o, out, out_size);
}